// round 10
// baseline (speedup 1.0000x reference)
#include <cuda_runtime.h>

// Uniform cubic B-spline via per-interval monomial (Horner) form.
// t = (x+1)*31.5 in [0,63], j = trunc(t), u = t-j,
// out = p0[j] + u*(p1[j] + u*(p2[j] + u*p3[j])), with
//   p0=(c0+4c1+c2)/6, p1=(c2-c0)/2, p2=(c0-2c1+c2)/2, p3=(c3-c0+3(c1-c2))/6.
// Table padded to 64 entries (entry 63 duplicates interval 62) -> no clamp.
// Shared table replicated 8x across the eight 16B bank groups: every LDS.128
// quarter-warp phase is conflict-free for random j.
// R10 = R5 backbone (single launch, occ-8, one wave, MLP=2) + padded table
// (no min on the critical path) + contiguous-pair global accesses (1KB/warp).

#define REP  8
#define NTBL 64

__device__ __forceinline__ float eval_one(float x, const float4* __restrict__ tp) {
    float t = fmaf(x, 31.5f, 31.5f);     // in [0, 63]
    int j = (int)t;                      // trunc == floor; 0..63 (table padded)
    float u = t - (float)j;
    float4 p = tp[j * REP];              // tp pre-offset by lane's bank-group
    return fmaf(fmaf(fmaf(p.w, u, p.z), u, p.y), u, p.x);
}

__device__ __forceinline__ float4 eval_four(float4 xv, const float4* __restrict__ tp) {
    float4 ov;
    ov.x = eval_one(xv.x, tp);
    ov.y = eval_one(xv.y, tp);
    ov.z = eval_one(xv.z, tp);
    ov.w = eval_one(xv.w, tp);
    return ov;
}

__global__ void __launch_bounds__(256, 8)
bspline_kernel(const float4* __restrict__ x4,
               const float* __restrict__ coeffs,
               float4* __restrict__ o4, int n2) {
    // n2 = number of contiguous float4 PAIRS (n/8)
    __shared__ float4 tbl[NTBL * REP];
    int tid = threadIdx.x;
    #pragma unroll
    for (int e = tid; e < NTBL * REP; e += 256) {
        int j = min(e >> 3, 62);         // entry 63 duplicates interval 62
        float c0 = __ldg(coeffs + j);
        float c1 = __ldg(coeffs + j + 1);
        float c2 = __ldg(coeffs + j + 2);
        float c3 = __ldg(coeffs + j + 3);
        float4 p;
        p.x = fmaf(4.0f, c1, c0 + c2) * 0.16666666666666666f;
        p.y = (c2 - c0) * 0.5f;
        p.z = fmaf(-2.0f, c1, c0 + c2) * 0.5f;
        p.w = fmaf(3.0f, c1 - c2, c3 - c0) * 0.16666666666666666f;
        tbl[e] = p;
    }
    __syncthreads();

    const float4* __restrict__ tp = tbl + (tid & (REP - 1));
    const int stride = gridDim.x * blockDim.x;

    // Each thread owns contiguous float4 pairs: warp covers 1KB per phase.
    for (int k = blockIdx.x * blockDim.x + tid; k < n2; k += stride) {
        int a = 2 * k;
        float4 xa0 = x4[a];
        float4 xa1 = x4[a + 1];
        float4 oa0 = eval_four(xa0, tp);
        float4 oa1 = eval_four(xa1, tp);
        o4[a]     = oa0;
        o4[a + 1] = oa1;
    }
}

extern "C" void kernel_launch(void* const* d_in, const int* in_sizes, int n_in,
                              void* d_out, int out_size) {
    const float* x      = (const float*)d_in[0];
    const float* coeffs = (const float*)d_in[1];
    float* out = (float*)d_out;
    int n  = in_sizes[0];
    int n2 = n >> 3;                 // float4 pairs; N = 2^22 divisible by 8
    int threads = 256;
    int blocks  = 1184;              // 8 CTAs/SM x 148 SMs = one exact wave
    int max_blocks = (n2 + threads - 1) / threads;
    if (blocks > max_blocks) blocks = max_blocks;
    if (blocks < 1) blocks = 1;
    bspline_kernel<<<blocks, threads>>>((const float4*)x, coeffs, (float4*)out, n2);
}

// round 11
// speedup vs baseline: 1.5364x; 1.5364x over previous
#include <cuda_runtime.h>

// Uniform cubic B-spline via per-interval monomial (Horner) form.
// t = (x+1)*31.5 in [0,63], j = trunc(t), u = t-j,
// out = p0[j] + u*(p1[j] + u*(p2[j] + u*p3[j])), with
//   p0=(c0+4c1+c2)/6, p1=(c2-c0)/2, p2=(c0-2c1+c2)/2, p3=(c3-c0+3(c1-c2))/6.
// Table padded to 64 entries (entry 63 dups interval 62) -> no clamp in loop.
// Shared table replicated 8x across the eight 16B bank groups: every LDS.128
// quarter-warp phase is conflict-free for random j.
//
// R11 = R5 backbone with max occupancy: 512-thread CTAs, 4 CTAs/SM = 64
// warps/SM, grid 592 = one exact wave, lane-interleaved MLP=2 (proven
// coalescing), half the prologues of R5.

#define REP  8
#define NTBL 64

__device__ __forceinline__ float eval_one(float x, const float4* __restrict__ tp) {
    float t = fmaf(x, 31.5f, 31.5f);     // in [0, 63]
    int j = (int)t;                      // trunc == floor; 0..63 (padded table)
    float u = t - (float)j;
    float4 p = tp[j * REP];              // tp pre-offset by lane's bank-group
    return fmaf(fmaf(fmaf(p.w, u, p.z), u, p.y), u, p.x);
}

__device__ __forceinline__ float4 eval_four(float4 xv, const float4* __restrict__ tp) {
    float4 ov;
    ov.x = eval_one(xv.x, tp);
    ov.y = eval_one(xv.y, tp);
    ov.z = eval_one(xv.z, tp);
    ov.w = eval_one(xv.w, tp);
    return ov;
}

__global__ void __launch_bounds__(512, 4)
bspline_kernel(const float4* __restrict__ x4,
               const float* __restrict__ coeffs,
               float4* __restrict__ o4, int n4) {
    __shared__ float4 tbl[NTBL * REP];
    int tid = threadIdx.x;
    // 512 entries / 512 threads: one entry each.
    {
        int j = min(tid >> 3, 62);       // entry 63 duplicates interval 62
        float c0 = __ldg(coeffs + j);
        float c1 = __ldg(coeffs + j + 1);
        float c2 = __ldg(coeffs + j + 2);
        float c3 = __ldg(coeffs + j + 3);
        float4 p;
        p.x = fmaf(4.0f, c1, c0 + c2) * 0.16666666666666666f;
        p.y = (c2 - c0) * 0.5f;
        p.z = fmaf(-2.0f, c1, c0 + c2) * 0.5f;
        p.w = fmaf(3.0f, c1 - c2, c3 - c0) * 0.16666666666666666f;
        tbl[tid] = p;
    }
    __syncthreads();

    const float4* __restrict__ tp = tbl + (tid & (REP - 1));
    const int stride = gridDim.x * blockDim.x;
    int i = blockIdx.x * blockDim.x + tid;

    // Lane-interleaved MLP=2: two independent, fully-coalesced float4 streams.
    for (; i + stride < n4; i += 2 * stride) {
        float4 xa = x4[i];
        float4 xb = x4[i + stride];
        o4[i]          = eval_four(xa, tp);
        o4[i + stride] = eval_four(xb, tp);
    }
    if (i < n4) {
        float4 xa = x4[i];
        o4[i] = eval_four(xa, tp);
    }
}

extern "C" void kernel_launch(void* const* d_in, const int* in_sizes, int n_in,
                              void* d_out, int out_size) {
    const float* x      = (const float*)d_in[0];
    const float* coeffs = (const float*)d_in[1];
    float* out = (float*)d_out;
    int n  = in_sizes[0];
    int n4 = n >> 2;                 // N = 2^22, divisible by 4
    int threads = 512;
    int blocks  = 592;               // 4 CTAs/SM x 148 SMs = one exact wave
    int max_blocks = (n4 + threads - 1) / threads;
    if (blocks > max_blocks) blocks = max_blocks;
    if (blocks < 1) blocks = 1;
    bspline_kernel<<<blocks, threads>>>((const float4*)x, coeffs, (float4*)out, n4);
}